// round 6
// baseline (speedup 1.0000x reference)
#include <cuda_runtime.h>
#include <cuda_fp16.h>

#define NN    100000
#define EEMAX 3200000
#define F1    16
#define F2    40
#define DIN   512
#define CAP   128               // bucket capacity; deg ~ Poisson(32), P(>128) ~ 0

// Scratch (static device globals — no allocation allowed)
__device__ int    g_cnt [NN];          // edge in-degree (without self-loop)
__device__ int    g_adj [NN * CAP];    // bucketed adjacency: sources per target
__device__ float  g_dinv[NN];
__device__ float  g_xw  [NN * F1];     // x @ W1 (fp32, unscaled)
__device__ __half g_src [NN * F1];     // fp16: dinv * xw
__device__ __half g_hds [NN * F1];     // fp16: dinv * dropout(h + b1)

// ---------------------------------------------------------------------------
// Single-pass adjacency build: count + bucket-append (no scan, no second pass)
__global__ void k_fill(const int* __restrict__ row, const int* __restrict__ col,
                       int E4, int E) {
    int i = blockIdx.x * blockDim.x + threadIdx.x;
    if (i < E4) {
        int4 r = ((const int4*)row)[i];
        int4 c = ((const int4*)col)[i];
        int p;
        p = atomicAdd(&g_cnt[c.x], 1); if (p < CAP) g_adj[c.x * CAP + p] = r.x;
        p = atomicAdd(&g_cnt[c.y], 1); if (p < CAP) g_adj[c.y * CAP + p] = r.y;
        p = atomicAdd(&g_cnt[c.z], 1); if (p < CAP) g_adj[c.z * CAP + p] = r.z;
        p = atomicAdd(&g_cnt[c.w], 1); if (p < CAP) g_adj[c.w * CAP + p] = r.w;
    } else {
        int e = E4 * 4 + (i - E4);               // tail (E%4 != 0 only)
        if (e < E) {
            int c = col[e], p = atomicAdd(&g_cnt[c], 1);
            if (p < CAP) g_adj[c * CAP + p] = row[e];
        }
    }
}

// ---------------------------------------------------------------------------
// gemm1: g_xw = x @ W1 (fp32; pure function of inputs -> forks at t=0)
__global__ __launch_bounds__(256) void k_gemm1(const float* __restrict__ x,
                                               const float* __restrict__ W1) {
    __shared__ float4 sW[DIN * 4];               // W1[512][16] as float4[512][4]
    const float4* Wv = (const float4*)W1;
    for (int i = threadIdx.x; i < DIN * 4; i += 256) sW[i] = Wv[i];
    __syncthreads();

    int v = blockIdx.x * 256 + threadIdx.x;
    if (v >= NN) return;

    float acc[16];
#pragma unroll
    for (int i = 0; i < 16; ++i) acc[i] = 0.0f;

    const float4* xr = (const float4*)(x + (size_t)v * DIN);
#pragma unroll 4
    for (int j = 0; j < DIN / 4; ++j) {
        float4 xv = xr[j];
#pragma unroll
        for (int u = 0; u < 4; ++u) {
            float xs = (u == 0) ? xv.x : (u == 1) ? xv.y : (u == 2) ? xv.z : xv.w;
            int k = j * 4 + u;
#pragma unroll
            for (int q = 0; q < 4; ++q) {
                float4 w = sW[k * 4 + q];
                acc[q * 4 + 0] += xs * w.x;
                acc[q * 4 + 1] += xs * w.y;
                acc[q * 4 + 2] += xs * w.z;
                acc[q * 4 + 3] += xs * w.w;
            }
        }
    }

    float4* sv = (float4*)(g_xw + (size_t)v * F1);
#pragma unroll
    for (int q = 0; q < 4; ++q)
        sv[q] = make_float4(acc[q*4], acc[q*4+1], acc[q*4+2], acc[q*4+3]);
}

// scale: dinv = rsqrt(cnt+1); g_src = fp16(dinv * g_xw)   (one thread per node)
__global__ void k_scale() {
    int v = blockIdx.x * blockDim.x + threadIdx.x;
    if (v >= NN) return;
    float d = rsqrtf((float)(g_cnt[v] + 1));
    g_dinv[v] = d;
    const float4* xp = (const float4*)(g_xw + (size_t)v * F1);
    uint4 o[2];
    __half2* hp = (__half2*)o;
#pragma unroll
    for (int q = 0; q < 4; ++q) {
        float4 a = xp[q];
        hp[q * 2 + 0] = __floats2half2_rn(d * a.x, d * a.y);
        hp[q * 2 + 1] = __floats2half2_rn(d * a.z, d * a.w);
    }
    ((uint4*)g_src)[v * 2 + 0] = o[0];
    ((uint4*)g_src)[v * 2 + 1] = o[1];
}

// ---------------------------------------------------------------------------
// JAX threefry2x32 (partitionable): key=(0,42), ctr=(0, idx).
// bernoulli(0.5) keep  <=>  MSB(out0 ^ out1) == 0
__device__ __forceinline__ unsigned tf_keep_bits(unsigned idx) {
    const unsigned k0 = 0u, k1 = 42u, k2 = 0u ^ 42u ^ 0x1BD11BDAu;
    unsigned x0 = k0;
    unsigned x1 = idx + k1;
#define TFR(r) { x0 += x1; x1 = (x1 << (r)) | (x1 >> (32 - (r))); x1 ^= x0; }
    TFR(13) TFR(15) TFR(26) TFR(6)   x0 += k1; x1 += k2 + 1u;
    TFR(17) TFR(29) TFR(16) TFR(24)  x0 += k2; x1 += k0 + 2u;
    TFR(13) TFR(15) TFR(26) TFR(6)   x0 += k0; x1 += k1 + 3u;
    TFR(17) TFR(29) TFR(16) TFR(24)  x0 += k1; x1 += k2 + 4u;
    TFR(13) TFR(15) TFR(26) TFR(6)   x0 += k2; x1 += k0 + 3u + 2u;
#undef TFR
    return x0 ^ x1;
}

// ---------------------------------------------------------------------------
// fp16 gather: 4 threads/node, q in [0,4) owns 4 halves (8B). 8-deep unroll.
__device__ __forceinline__ void h4acc(uint2 u, float4& acc) {
    float2 f0 = __half22float2(*(__half2*)&u.x);
    float2 f1 = __half22float2(*(__half2*)&u.y);
    acc.x += f0.x; acc.y += f0.y; acc.z += f1.x; acc.w += f1.y;
}

#define AGG_LOOP(SRCP)                                                         \
    float4 acc = make_float4(0.f, 0.f, 0.f, 0.f);                              \
    { uint2 us = SRCP[t * 4 + q]; h4acc(us, acc); }   /* self-loop */          \
    {                                                                          \
        int cnt = g_cnt[t]; if (cnt > CAP) cnt = CAP;                          \
        const int* ap = g_adj + t * CAP;                                       \
        int pos = 0;                                                           \
        for (; pos + 8 <= cnt; pos += 8) {                                     \
            int r0 = ap[pos+0], r1 = ap[pos+1], r2 = ap[pos+2], r3 = ap[pos+3];\
            int r4 = ap[pos+4], r5 = ap[pos+5], r6 = ap[pos+6], r7 = ap[pos+7];\
            uint2 u0 = SRCP[r0*4+q], u1 = SRCP[r1*4+q];                        \
            uint2 u2 = SRCP[r2*4+q], u3 = SRCP[r3*4+q];                        \
            uint2 u4 = SRCP[r4*4+q], u5 = SRCP[r5*4+q];                        \
            uint2 u6 = SRCP[r6*4+q], u7 = SRCP[r7*4+q];                        \
            h4acc(u0, acc); h4acc(u1, acc); h4acc(u2, acc); h4acc(u3, acc);    \
            h4acc(u4, acc); h4acc(u5, acc); h4acc(u6, acc); h4acc(u7, acc);    \
        }                                                                      \
        for (; pos < cnt; ++pos) { uint2 u = SRCP[ap[pos]*4+q]; h4acc(u, acc);}\
    }

// Layer-1 aggregation (4 threads per node) + dropout fused; fp16 out.
__global__ __launch_bounds__(256) void k_agg1(const float* __restrict__ b1) {
    int t = blockIdx.x * 64 + (threadIdx.x >> 2);
    int q = threadIdx.x & 3;
    if (t >= NN) return;

    const uint2* src = (const uint2*)g_src;
    AGG_LOOP(src)

    float d = g_dinv[t];
    float4 bb = ((const float4*)b1)[q];
    unsigned idx = (unsigned)(t * 16 + q * 4);
    float h0 = d * acc.x + bb.x, h1 = d * acc.y + bb.y;
    float h2 = d * acc.z + bb.z, h3 = d * acc.w + bb.w;
    float o0 = (tf_keep_bits(idx + 0) & 0x80000000u) ? 0.0f : 2.0f * d * h0;
    float o1 = (tf_keep_bits(idx + 1) & 0x80000000u) ? 0.0f : 2.0f * d * h1;
    float o2 = (tf_keep_bits(idx + 2) & 0x80000000u) ? 0.0f : 2.0f * d * h2;
    float o3 = (tf_keep_bits(idx + 3) & 0x80000000u) ? 0.0f : 2.0f * d * h3;
    uint2 o;
    ((__half2*)&o.x)[0] = __floats2half2_rn(o0, o1);
    ((__half2*)&o.y)[0] = __floats2half2_rn(o2, o3);
    ((uint2*)g_hds)[t * 4 + q] = o;
}

// Layer-2 aggregation + fused (16x40 GEMM + b2); fp32 out written directly.
__global__ __launch_bounds__(256) void k_agg2(const float* __restrict__ W2,
                                              const float* __restrict__ b2,
                                              float* __restrict__ out) {
    __shared__ float sW[F1 * F2];
    __shared__ float sb[F2];
    for (int i = threadIdx.x; i < F1 * F2; i += 256) sW[i] = W2[i];
    if (threadIdx.x < F2) sb[threadIdx.x] = b2[threadIdx.x];
    __syncthreads();

    int tid = blockIdx.x * 64 + (threadIdx.x >> 2);
    int q   = threadIdx.x & 3;
    bool valid = tid < NN;
    int t = valid ? tid : NN - 1;

    const uint2* src = (const uint2*)g_hds;
    AGG_LOOP(src)

    float d = g_dinv[t];
    acc.x *= d; acc.y *= d; acc.z *= d; acc.w *= d;

    // assemble all 16 features into each lane via width-4 shuffles
    float gg[16];
#pragma unroll
    for (int s = 0; s < 4; ++s) {
        gg[s*4+0] = __shfl_sync(0xffffffffu, acc.x, s, 4);
        gg[s*4+1] = __shfl_sync(0xffffffffu, acc.y, s, 4);
        gg[s*4+2] = __shfl_sync(0xffffffffu, acc.z, s, 4);
        gg[s*4+3] = __shfl_sync(0xffffffffu, acc.w, s, 4);
    }

    // each lane computes 10 of the 40 outputs
    float o[10];
#pragma unroll
    for (int j = 0; j < 10; ++j) o[j] = sb[q * 10 + j];
#pragma unroll
    for (int k = 0; k < 16; ++k) {
        float gv = gg[k];
        const float* wr = sW + k * F2 + q * 10;
#pragma unroll
        for (int j = 0; j < 10; ++j) o[j] += gv * wr[j];
    }

    if (valid) {
        float* op = out + (size_t)t * F2 + q * 10;
#pragma unroll
        for (int j = 0; j < 10; ++j) op[j] = o[j];
    }
}

// ---------------------------------------------------------------------------
extern "C" void kernel_launch(void* const* d_in, const int* in_sizes, int n_in,
                              void* d_out, int out_size) {
    const float* x  = (const float*)d_in[0];
    const int*   ei = (const int*)  d_in[1];
    const float* W1 = (const float*)d_in[2];
    const float* b1 = (const float*)d_in[3];
    const float* W2 = (const float*)d_in[4];
    const float* b2 = (const float*)d_in[5];
    float* out = (float*)d_out;

    int E = in_sizes[1] / 2;                  // 3,200,000
    if (E > EEMAX) E = EEMAX;
    const int* row = ei;
    const int* col = ei + E;
    int E4 = E / 4;

    const int TB = 256;
    int nb_n  = (NN + TB - 1) / TB;
    int nb_e4 = (E4 + (E - E4 * 4) + TB - 1) / TB;
    int nb_a  = (NN + 63) / 64;               // agg blocks (4 thr/node)

    // one-time host-side resources (created on first call, reused by capture)
    static cudaStream_t sB = nullptr;
    static cudaEvent_t evStart = nullptr, evGemm = nullptr;
    static void* cntPtr = nullptr;
    if (!sB) {
        cudaStreamCreateWithFlags(&sB, cudaStreamNonBlocking);
        cudaEventCreateWithFlags(&evStart, cudaEventDisableTiming);
        cudaEventCreateWithFlags(&evGemm,  cudaEventDisableTiming);
        cudaGetSymbolAddress(&cntPtr, g_cnt);
    }

    // side stream: gemm1 has zero upstream deps -> starts at t=0
    cudaEventRecord(evStart, 0);
    cudaStreamWaitEvent(sB, evStart, 0);
    k_gemm1 <<<nb_n, TB, 0, sB>>>(x, W1);     // g_xw = x @ W1
    cudaEventRecord(evGemm, sB);

    // main stream: one-pass bucketed adjacency build
    cudaMemsetAsync(cntPtr, 0, NN * sizeof(int), 0);
    k_fill  <<<nb_e4, TB>>>(row, col, E4, E);

    cudaStreamWaitEvent(0, evGemm, 0);        // join gemm1
    k_scale <<<nb_n, TB>>>();                 // dinv + fp16 scaled src
    k_agg1  <<<nb_a, TB>>>(b1);               // g_hds (dropout fused)
    k_agg2  <<<nb_a, TB>>>(W2, b2, out);      // out (GEMM fused)
}

// round 7
// speedup vs baseline: 1.0631x; 1.0631x over previous
#include <cuda_runtime.h>
#include <cuda_fp16.h>

#define NN    100000
#define EEMAX 3200000
#define F1    16
#define F2    40
#define DIN   512
#define CAP   128               // bucket capacity; deg ~ Poisson(32), P(>128) ~ 0

// Scratch (static device globals — no allocation allowed)
__device__ int    g_cnt [NN];          // edge in-degree (without self-loop)
__device__ int    g_adj [NN * CAP];    // bucketed adjacency: sources per target
__device__ float  g_dinv[NN];
__device__ float  g_xw  [NN * F1];     // x @ W1 (fp32, unscaled)
__device__ __half g_src [NN * F1];     // fp16: dinv * xw
__device__ __half g_hds [NN * F1];     // fp16: dinv * dropout(h + b1)

// packed f32x2 helpers (Blackwell FFMA2 path — PTX-only per SASS_PATTERNS)
#define PACK2(dst, lo, hi) \
    asm("mov.b64 %0, {%1, %2};" : "=l"(dst) : "f"(lo), "f"(hi))
#define UNPACK2(lo, hi, src) \
    asm("mov.b64 {%0, %1}, %2;" : "=f"(lo), "=f"(hi) : "l"(src))
#define FMA2(acc, a, b) \
    asm("fma.rn.f32x2 %0, %1, %2, %0;" : "+l"(acc) : "l"(a), "l"(b))

// ---------------------------------------------------------------------------
// Single-pass adjacency build: count + bucket-append (no scan, no second pass)
__global__ void k_fill(const int* __restrict__ row, const int* __restrict__ col,
                       int E4, int E) {
    int i = blockIdx.x * blockDim.x + threadIdx.x;
    if (i < E4) {
        int4 r = ((const int4*)row)[i];
        int4 c = ((const int4*)col)[i];
        int p;
        p = atomicAdd(&g_cnt[c.x], 1); if (p < CAP) g_adj[c.x * CAP + p] = r.x;
        p = atomicAdd(&g_cnt[c.y], 1); if (p < CAP) g_adj[c.y * CAP + p] = r.y;
        p = atomicAdd(&g_cnt[c.z], 1); if (p < CAP) g_adj[c.z * CAP + p] = r.z;
        p = atomicAdd(&g_cnt[c.w], 1); if (p < CAP) g_adj[c.w * CAP + p] = r.w;
    } else {
        int e = E4 * 4 + (i - E4);               // tail (E%4 != 0 only)
        if (e < E) {
            int c = col[e], p = atomicAdd(&g_cnt[c], 1);
            if (p < CAP) g_adj[c * CAP + p] = row[e];
        }
    }
}

// ---------------------------------------------------------------------------
// gemm1: g_xw = x @ W1 via packed FFMA2 (pure function of inputs; forks at t=0)
__global__ __launch_bounds__(256) void k_gemm1(const float* __restrict__ x,
                                               const float* __restrict__ W1) {
    // W1[512][16] pre-packed as f32x2 pairs: sWp[k*4+q] = {(f4q,f4q+1),(f4q+2,f4q+3)}
    __shared__ ulonglong2 sWp[DIN * 4];
    const float4* Wv = (const float4*)W1;
    for (int i = threadIdx.x; i < DIN * 4; i += 256) {
        float4 w = Wv[i];
        ulonglong2 p;
        PACK2(p.x, w.x, w.y);
        PACK2(p.y, w.z, w.w);
        sWp[i] = p;
    }
    __syncthreads();

    int v = blockIdx.x * 256 + threadIdx.x;
    if (v >= NN) return;

    unsigned long long acc2[8];                  // 8 × f32x2 = 16 fp32 accums
#pragma unroll
    for (int i = 0; i < 8; ++i) acc2[i] = 0ull;  // (0.0f, 0.0f)

    const float4* xr = (const float4*)(x + (size_t)v * DIN);
#pragma unroll 4
    for (int j = 0; j < DIN / 4; ++j) {
        float4 xv = xr[j];
#pragma unroll
        for (int u = 0; u < 4; ++u) {
            float xs = (u == 0) ? xv.x : (u == 1) ? xv.y : (u == 2) ? xv.z : xv.w;
            unsigned long long xx;
            PACK2(xx, xs, xs);
            int k = j * 4 + u;
#pragma unroll
            for (int q = 0; q < 4; ++q) {
                ulonglong2 w = sWp[k * 4 + q];
                FMA2(acc2[q * 2 + 0], w.x, xx);
                FMA2(acc2[q * 2 + 1], w.y, xx);
            }
        }
    }

    float4* sv = (float4*)(g_xw + (size_t)v * F1);
#pragma unroll
    for (int q = 0; q < 4; ++q) {
        float4 a;
        UNPACK2(a.x, a.y, acc2[q * 2 + 0]);
        UNPACK2(a.z, a.w, acc2[q * 2 + 1]);
        sv[q] = a;
    }
}

// scale: dinv = rsqrt(cnt+1); g_src = fp16(dinv * g_xw)   (one thread per node)
__global__ void k_scale() {
    int v = blockIdx.x * blockDim.x + threadIdx.x;
    if (v >= NN) return;
    float d = rsqrtf((float)(g_cnt[v] + 1));
    g_dinv[v] = d;
    const float4* xp = (const float4*)(g_xw + (size_t)v * F1);
    uint4 o[2];
    __half2* hp = (__half2*)o;
#pragma unroll
    for (int q = 0; q < 4; ++q) {
        float4 a = xp[q];
        hp[q * 2 + 0] = __floats2half2_rn(d * a.x, d * a.y);
        hp[q * 2 + 1] = __floats2half2_rn(d * a.z, d * a.w);
    }
    ((uint4*)g_src)[v * 2 + 0] = o[0];
    ((uint4*)g_src)[v * 2 + 1] = o[1];
}

// ---------------------------------------------------------------------------
// JAX threefry2x32 (partitionable): key=(0,42), ctr=(0, idx).
// bernoulli(0.5) keep  <=>  MSB(out0 ^ out1) == 0
__device__ __forceinline__ unsigned tf_keep_bits(unsigned idx) {
    const unsigned k0 = 0u, k1 = 42u, k2 = 0u ^ 42u ^ 0x1BD11BDAu;
    unsigned x0 = k0;
    unsigned x1 = idx + k1;
#define TFR(r) { x0 += x1; x1 = (x1 << (r)) | (x1 >> (32 - (r))); x1 ^= x0; }
    TFR(13) TFR(15) TFR(26) TFR(6)   x0 += k1; x1 += k2 + 1u;
    TFR(17) TFR(29) TFR(16) TFR(24)  x0 += k2; x1 += k0 + 2u;
    TFR(13) TFR(15) TFR(26) TFR(6)   x0 += k0; x1 += k1 + 3u;
    TFR(17) TFR(29) TFR(16) TFR(24)  x0 += k1; x1 += k2 + 4u;
    TFR(13) TFR(15) TFR(26) TFR(6)   x0 += k2; x1 += k0 + 5u;
#undef TFR
    return x0 ^ x1;
}

// ---------------------------------------------------------------------------
// fp16 gather: 4 threads/node, q in [0,4) owns 4 halves (8B). 8-deep unroll,
// adjacency read as int4 (2 LDG.128 per quad per iter).
__device__ __forceinline__ void h4acc(uint2 u, float4& acc) {
    float2 f0 = __half22float2(*(__half2*)&u.x);
    float2 f1 = __half22float2(*(__half2*)&u.y);
    acc.x += f0.x; acc.y += f0.y; acc.z += f1.x; acc.w += f1.y;
}

#define AGG_LOOP(SRCP)                                                         \
    float4 acc = make_float4(0.f, 0.f, 0.f, 0.f);                              \
    { uint2 us = SRCP[t * 4 + q]; h4acc(us, acc); }   /* self-loop */          \
    {                                                                          \
        int cnt = g_cnt[t]; if (cnt > CAP) cnt = CAP;                          \
        const int* ap = g_adj + t * CAP;                                       \
        int pos = 0;                                                           \
        for (; pos + 8 <= cnt; pos += 8) {                                     \
            int4 a0 = ((const int4*)(ap + pos))[0];                            \
            int4 a1 = ((const int4*)(ap + pos))[1];                            \
            uint2 u0 = SRCP[a0.x*4+q], u1 = SRCP[a0.y*4+q];                    \
            uint2 u2 = SRCP[a0.z*4+q], u3 = SRCP[a0.w*4+q];                    \
            uint2 u4 = SRCP[a1.x*4+q], u5 = SRCP[a1.y*4+q];                    \
            uint2 u6 = SRCP[a1.z*4+q], u7 = SRCP[a1.w*4+q];                    \
            h4acc(u0, acc); h4acc(u1, acc); h4acc(u2, acc); h4acc(u3, acc);    \
            h4acc(u4, acc); h4acc(u5, acc); h4acc(u6, acc); h4acc(u7, acc);    \
        }                                                                      \
        for (; pos < cnt; ++pos) { uint2 u = SRCP[ap[pos]*4+q]; h4acc(u, acc);}\
    }

// Layer-1 aggregation (4 threads per node) + dropout fused; fp16 out.
__global__ __launch_bounds__(256) void k_agg1(const float* __restrict__ b1) {
    int t = blockIdx.x * 64 + (threadIdx.x >> 2);
    int q = threadIdx.x & 3;
    if (t >= NN) return;

    const uint2* src = (const uint2*)g_src;
    AGG_LOOP(src)

    float d = g_dinv[t];
    float4 bb = ((const float4*)b1)[q];
    unsigned idx = (unsigned)(t * 16 + q * 4);
    float h0 = d * acc.x + bb.x, h1 = d * acc.y + bb.y;
    float h2 = d * acc.z + bb.z, h3 = d * acc.w + bb.w;
    float o0 = (tf_keep_bits(idx + 0) & 0x80000000u) ? 0.0f : 2.0f * d * h0;
    float o1 = (tf_keep_bits(idx + 1) & 0x80000000u) ? 0.0f : 2.0f * d * h1;
    float o2 = (tf_keep_bits(idx + 2) & 0x80000000u) ? 0.0f : 2.0f * d * h2;
    float o3 = (tf_keep_bits(idx + 3) & 0x80000000u) ? 0.0f : 2.0f * d * h3;
    uint2 o;
    ((__half2*)&o.x)[0] = __floats2half2_rn(o0, o1);
    ((__half2*)&o.y)[0] = __floats2half2_rn(o2, o3);
    ((uint2*)g_hds)[t * 4 + q] = o;
}

// Layer-2 aggregation + fused (16x40 GEMM + b2); fp32 out written directly.
__global__ __launch_bounds__(256) void k_agg2(const float* __restrict__ W2,
                                              const float* __restrict__ b2,
                                              float* __restrict__ out) {
    __shared__ float sW[F1 * F2];
    __shared__ float sb[F2];
    for (int i = threadIdx.x; i < F1 * F2; i += 256) sW[i] = W2[i];
    if (threadIdx.x < F2) sb[threadIdx.x] = b2[threadIdx.x];
    __syncthreads();

    int tid = blockIdx.x * 64 + (threadIdx.x >> 2);
    int q   = threadIdx.x & 3;
    bool valid = tid < NN;
    int t = valid ? tid : NN - 1;

    const uint2* src = (const uint2*)g_hds;
    AGG_LOOP(src)

    float d = g_dinv[t];
    acc.x *= d; acc.y *= d; acc.z *= d; acc.w *= d;

    // assemble all 16 features into each lane via width-4 shuffles
    float gg[16];
#pragma unroll
    for (int s = 0; s < 4; ++s) {
        gg[s*4+0] = __shfl_sync(0xffffffffu, acc.x, s, 4);
        gg[s*4+1] = __shfl_sync(0xffffffffu, acc.y, s, 4);
        gg[s*4+2] = __shfl_sync(0xffffffffu, acc.z, s, 4);
        gg[s*4+3] = __shfl_sync(0xffffffffu, acc.w, s, 4);
    }

    // each lane computes 10 of the 40 outputs
    float o[10];
#pragma unroll
    for (int j = 0; j < 10; ++j) o[j] = sb[q * 10 + j];
#pragma unroll
    for (int k = 0; k < 16; ++k) {
        float gv = gg[k];
        const float* wr = sW + k * F2 + q * 10;
#pragma unroll
        for (int j = 0; j < 10; ++j) o[j] += gv * wr[j];
    }

    if (valid) {
        float* op = out + (size_t)t * F2 + q * 10;
#pragma unroll
        for (int j = 0; j < 10; ++j) op[j] = o[j];
    }
}

// ---------------------------------------------------------------------------
extern "C" void kernel_launch(void* const* d_in, const int* in_sizes, int n_in,
                              void* d_out, int out_size) {
    const float* x  = (const float*)d_in[0];
    const int*   ei = (const int*)  d_in[1];
    const float* W1 = (const float*)d_in[2];
    const float* b1 = (const float*)d_in[3];
    const float* W2 = (const float*)d_in[4];
    const float* b2 = (const float*)d_in[5];
    float* out = (float*)d_out;

    int E = in_sizes[1] / 2;                  // 3,200,000
    if (E > EEMAX) E = EEMAX;
    const int* row = ei;
    const int* col = ei + E;
    int E4 = E / 4;

    const int TB = 256;
    int nb_n  = (NN + TB - 1) / TB;
    int nb_e4 = (E4 + (E - E4 * 4) + TB - 1) / TB;
    int nb_a  = (NN + 63) / 64;               // agg blocks (4 thr/node)

    // one-time host-side resources (created on first call, reused by capture)
    static cudaStream_t sB = nullptr;
    static cudaEvent_t evStart = nullptr, evGemm = nullptr;
    static void* cntPtr = nullptr;
    if (!sB) {
        cudaStreamCreateWithFlags(&sB, cudaStreamNonBlocking);
        cudaEventCreateWithFlags(&evStart, cudaEventDisableTiming);
        cudaEventCreateWithFlags(&evGemm,  cudaEventDisableTiming);
        cudaGetSymbolAddress(&cntPtr, g_cnt);
    }

    // side stream: gemm1 has zero upstream deps -> starts at t=0
    cudaEventRecord(evStart, 0);
    cudaStreamWaitEvent(sB, evStart, 0);
    k_gemm1 <<<nb_n, TB, 0, sB>>>(x, W1);     // g_xw = x @ W1 (FFMA2)
    cudaEventRecord(evGemm, sB);

    // main stream: one-pass bucketed adjacency build
    cudaMemsetAsync(cntPtr, 0, NN * sizeof(int), 0);
    k_fill  <<<nb_e4, TB>>>(row, col, E4, E);

    cudaStreamWaitEvent(0, evGemm, 0);        // join gemm1
    k_scale <<<nb_n, TB>>>();                 // dinv + fp16 scaled src
    k_agg1  <<<nb_a, TB>>>(b1);               // g_hds (dropout fused)
    k_agg2  <<<nb_a, TB>>>(W2, b2, out);      // out (GEMM fused)
}